// round 1
// baseline (speedup 1.0000x reference)
#include <cuda_runtime.h>
#include <cstddef>

#define B_ 32
#define C_ 32
#define N_ 512
#define T_ 480
#define BT_ (B_*T_)          // 15360
#define STAT_CHUNKS 120
#define ROWS_PER_CHUNK (BT_/STAT_CHUNKS)   // 128

// ---------------- scratch (static device arrays; no allocations) ----------------
__device__ float g_f2[B_*C_*T_];        // [b][c][t]   2 MB
__device__ float g_tmp[B_*C_*T_];       // [b][c][t]   2 MB
__device__ float g_logits[(size_t)B_*T_*T_];  // [b][t][s]  28 MB
__device__ float g_out2[(size_t)B_*T_*T_];    // [b][t][u]  28 MB
__device__ float g_psum[STAT_CHUNKS*T_];
__device__ float g_psumsq[STAT_CHUNKS*T_];
__device__ float g_scale[T_];
__device__ float g_shift[T_];

// ================================================================================
// K1: single pass over seq  ->  f2[b,c,t] = sum_n w2[n]*seq[b,c,n,t]
//                               tmp[b,c,t] = sum_n w[n,c] * (sum_c' w1[c']*seq[b,c',n,t])
// Block = (t-chunk of 32, b). 256 threads = 32 t-lanes x 8 n-groups.
// Each thread owns one t, an n-subset of 64, all 32 c.  n-reduction in smem.
// ================================================================================
__global__ __launch_bounds__(256, 2)
void k1_fused(const float* __restrict__ seq, const float* __restrict__ w1,
              const float* __restrict__ w2, const float* __restrict__ w)
{
    __shared__ float sbuf[32*8*32];   // 32KB; phases: w tile (4096 floats); end: reduction buffer
    __shared__ float w1s[32];
    __shared__ float w2s[N_];

    const int tid = threadIdx.x;
    const int tt  = tid & 31;      // t lane within chunk
    const int ng  = tid >> 5;      // n group 0..7
    const int tc  = blockIdx.x;    // 0..14
    const int b   = blockIdx.y;    // 0..31
    const int t   = tc*32 + tt;

    if (tid < 32) w1s[tid] = w1[tid];
    for (int i = tid; i < N_; i += 256) w2s[i] = w2[i];

    float f2loc[32], tmploc[32];
    #pragma unroll
    for (int c = 0; c < 32; ++c) { f2loc[c] = 0.f; tmploc[c] = 0.f; }

    const float* seqb = seq + (size_t)b*C_*N_*T_ + t;

    for (int ph = 0; ph < 4; ++ph) {
        __syncthreads();                                   // protect w tile (and w1s/w2s on ph=0)
        for (int i = tid; i < 128*32; i += 256)
            sbuf[i] = w[ph*128*32 + i];
        __syncthreads();

        const int nbase = ph*128 + ng*16;
        for (int j = 0; j < 16; ++j) {
            const int n = nbase + j;
            const float* p = seqb + (size_t)n*T_;
            const float w2n = w2s[n];
            float f1acc = 0.f;
            #pragma unroll
            for (int c = 0; c < 32; ++c) {
                float v = p[(size_t)c*N_*T_];
                f1acc    = fmaf(w1s[c], v, f1acc);
                f2loc[c] = fmaf(w2n,    v, f2loc[c]);
            }
            const float* wr = &sbuf[(n - ph*128)*32];
            #pragma unroll
            for (int c = 0; c < 32; ++c)
                tmploc[c] = fmaf(wr[c], f1acc, tmploc[c]);
        }
    }

    // ---- deterministic in-block reduction over the 8 n-groups ----
    __syncthreads();
    #pragma unroll
    for (int c = 0; c < 32; ++c) sbuf[c*256 + ng*32 + tt] = f2loc[c];
    __syncthreads();
    #pragma unroll
    for (int k = 0; k < 4; ++k) {
        const int o = tid + k*256;
        const int c = o >> 5, t2 = o & 31;
        float s = 0.f;
        #pragma unroll
        for (int g = 0; g < 8; ++g) s += sbuf[c*256 + g*32 + t2];
        g_f2[((size_t)b*C_ + c)*T_ + tc*32 + t2] = s;
    }
    __syncthreads();
    #pragma unroll
    for (int c = 0; c < 32; ++c) sbuf[c*256 + ng*32 + tt] = tmploc[c];
    __syncthreads();
    #pragma unroll
    for (int k = 0; k < 4; ++k) {
        const int o = tid + k*256;
        const int c = o >> 5, t2 = o & 31;
        float s = 0.f;
        #pragma unroll
        for (int g = 0; g < 8; ++g) s += sbuf[c*256 + g*32 + t2];
        g_tmp[((size_t)b*C_ + c)*T_ + tc*32 + t2] = s;
    }
}

// ================================================================================
// K2: logits[b,t,s] = sigmoid( sum_c tmp[b,c,t]*f2[b,c,s] + bmat[t,s] )
// Block = (t-chunk of 32, b), 480 threads = s.
// ================================================================================
__global__ __launch_bounds__(480)
void k2_logits(const float* __restrict__ bmat)
{
    __shared__ float tmps[32*32];  // [c][tt]
    const int s  = threadIdx.x;
    const int tc = blockIdx.x;
    const int b  = blockIdx.y;

    for (int i = s; i < 1024; i += 480) {
        const int c = i >> 5, tt = i & 31;
        tmps[i] = g_tmp[((size_t)b*C_ + c)*T_ + tc*32 + tt];
    }
    __syncthreads();

    float f2r[32];
    #pragma unroll
    for (int c = 0; c < 32; ++c) f2r[c] = g_f2[((size_t)b*C_ + c)*T_ + s];

    for (int tg = 0; tg < 8; ++tg) {
        const int t0 = tc*32 + tg*4;
        float a0 = bmat[(size_t)(t0+0)*T_ + s];
        float a1 = bmat[(size_t)(t0+1)*T_ + s];
        float a2 = bmat[(size_t)(t0+2)*T_ + s];
        float a3 = bmat[(size_t)(t0+3)*T_ + s];
        #pragma unroll
        for (int c = 0; c < 32; ++c) {
            float4 tv = *reinterpret_cast<const float4*>(&tmps[c*32 + tg*4]);
            const float f = f2r[c];
            a0 = fmaf(tv.x, f, a0);
            a1 = fmaf(tv.y, f, a1);
            a2 = fmaf(tv.z, f, a2);
            a3 = fmaf(tv.w, f, a3);
        }
        const size_t o = ((size_t)b*T_ + t0)*T_ + s;
        g_logits[o        ] = 1.f/(1.f + __expf(-a0));
        g_logits[o +   T_ ] = 1.f/(1.f + __expf(-a1));
        g_logits[o + 2*T_ ] = 1.f/(1.f + __expf(-a2));
        g_logits[o + 3*T_ ] = 1.f/(1.f + __expf(-a3));
    }
}

// ================================================================================
// K3: out2[b,t,u] = sum_s v[t,s] * logits[b,s,u]    (32 x [480x480]@[480x480])
// 96x96 tile, BK=16, 16x16 threads, 6x6 register tile. fp32 SIMT.
// ================================================================================
__global__ __launch_bounds__(256)
void k3_gemm(const float* __restrict__ v)
{
    __shared__ float vsT[16][97];   // [k][t-row], padded
    __shared__ float Ls [16][97];   // [k][u],     padded

    const int tid = threadIdx.x;
    const int tr  = tid >> 4;       // 0..15
    const int tc  = tid & 15;       // 0..15
    const int u0  = blockIdx.x * 96;
    const int t0  = blockIdx.y * 96;
    const int b   = blockIdx.z;
    const float* Lb = g_logits + (size_t)b*T_*T_;

    float acc[6][6];
    #pragma unroll
    for (int i = 0; i < 6; ++i)
        #pragma unroll
        for (int j = 0; j < 6; ++j) acc[i][j] = 0.f;

    for (int k0 = 0; k0 < T_; k0 += 16) {
        #pragma unroll
        for (int r = 0; r < 6; ++r) {          // 96x16 v tile (transposed store)
            const int i = tid + r*256;
            const int kk = i & 15, row = i >> 4;
            vsT[kk][row] = v[(size_t)(t0 + row)*T_ + k0 + kk];
        }
        #pragma unroll
        for (int r = 0; r < 6; ++r) {          // 16x96 L tile
            const int i = tid + r*256;
            const int kk = i / 96, uu = i - kk*96;
            Ls[kk][uu] = Lb[(size_t)(k0 + kk)*T_ + u0 + uu];
        }
        __syncthreads();
        #pragma unroll
        for (int kk = 0; kk < 16; ++kk) {
            float a[6], bb[6];
            #pragma unroll
            for (int i = 0; i < 6; ++i) a[i]  = vsT[kk][tr*6 + i];
            #pragma unroll
            for (int j = 0; j < 6; ++j) bb[j] = Ls[kk][tc*6 + j];
            #pragma unroll
            for (int i = 0; i < 6; ++i)
                #pragma unroll
                for (int j = 0; j < 6; ++j)
                    acc[i][j] = fmaf(a[i], bb[j], acc[i][j]);
        }
        __syncthreads();
    }

    float* ob = g_out2 + ((size_t)b*T_ + t0 + tr*6)*T_ + u0 + tc*6;
    #pragma unroll
    for (int i = 0; i < 6; ++i) {
        #pragma unroll
        for (int j = 0; j < 6; j += 2) {       // float2 stores (8B-aligned)
            float2 p; p.x = acc[i][j]; p.y = acc[i][j+1];
            *reinterpret_cast<float2*>(&ob[(size_t)i*T_ + j]) = p;
        }
    }
}

// ================================================================================
// K4/K5: BatchNorm batch stats over (b,t) per u — deterministic two-stage.
// ================================================================================
__global__ __launch_bounds__(480)
void k4_stats()
{
    const int u  = threadIdx.x;
    const int ch = blockIdx.x;
    const float* base = g_out2 + (size_t)ch*ROWS_PER_CHUNK*T_ + u;
    float s = 0.f, q = 0.f;
    for (int r = 0; r < ROWS_PER_CHUNK; ++r) {
        const float x = base[(size_t)r*T_];
        s += x;
        q = fmaf(x, x, q);
    }
    g_psum  [ch*T_ + u] = s;
    g_psumsq[ch*T_ + u] = q;
}

__global__ __launch_bounds__(512)
void k5_final(const float* __restrict__ gamma, const float* __restrict__ beta)
{
    const int u = threadIdx.x;
    if (u >= T_) return;
    float s = 0.f, q = 0.f;
    for (int ch = 0; ch < STAT_CHUNKS; ++ch) { s += g_psum[ch*T_+u]; q += g_psumsq[ch*T_+u]; }
    const float mean = s * (1.f/(float)BT_);
    const float var  = q * (1.f/(float)BT_) - mean*mean;
    const float sc   = gamma[u] * rsqrtf(var + 1e-5f);
    g_scale[u] = sc;
    g_shift[u] = beta[u] - mean*sc;
}

// ================================================================================
// K6: out[b,t,u] = softmax_u( out2*scale + shift + mask[t,u] )
// One block per (b,t) row. Inputs are BN-standardized => no max-subtraction needed.
// ================================================================================
__global__ __launch_bounds__(512)
void k6_softmax(const float* __restrict__ mask, float* __restrict__ out)
{
    __shared__ float red[16];
    const int row = blockIdx.x;          // b*T_ + t
    const int t   = row % T_;
    const int tid = threadIdx.x;

    float e = 0.f;
    if (tid < T_) {
        const float x = g_out2[(size_t)row*T_ + tid] * g_scale[tid] + g_shift[tid]
                      + mask[(size_t)t*T_ + tid];
        e = __expf(x);                   // exp(-1e13) -> 0 for masked entries
    }
    float s = e;
    #pragma unroll
    for (int o = 16; o > 0; o >>= 1) s += __shfl_xor_sync(0xffffffffu, s, o);
    if ((tid & 31) == 0) red[tid >> 5] = s;
    __syncthreads();
    if (tid < 32) {
        float v2 = (tid < 16) ? red[tid] : 0.f;
        #pragma unroll
        for (int o = 8; o > 0; o >>= 1) v2 += __shfl_xor_sync(0xffffffffu, v2, o);
        if (tid == 0) red[0] = v2;
    }
    __syncthreads();
    const float inv = 1.f / red[0];
    if (tid < T_) out[(size_t)row*T_ + tid] = e * inv;
}

// ================================================================================
extern "C" void kernel_launch(void* const* d_in, const int* in_sizes, int n_in,
                              void* d_out, int out_size)
{
    const float* seq   = (const float*)d_in[0];
    const float* w1    = (const float*)d_in[1];
    const float* w2    = (const float*)d_in[2];
    const float* w     = (const float*)d_in[3];
    const float* bmat  = (const float*)d_in[4];
    const float* v     = (const float*)d_in[5];
    const float* gamma = (const float*)d_in[6];
    const float* beta  = (const float*)d_in[7];
    const float* mask  = (const float*)d_in[8];
    float* out = (float*)d_out;

    k1_fused  <<<dim3(15, 32), 256>>>(seq, w1, w2, w);
    k2_logits <<<dim3(15, 32), 480>>>(bmat);
    k3_gemm   <<<dim3(5, 5, 32), 256>>>(v);
    k4_stats  <<<STAT_CHUNKS, 480>>>();
    k5_final  <<<1, 512>>>(gamma, beta);
    k6_softmax<<<BT_, 512>>>(mask, out);
}

// round 2
// speedup vs baseline: 1.1284x; 1.1284x over previous
#include <cuda_runtime.h>
#include <cstddef>

#define B_ 32
#define C_ 32
#define N_ 512
#define T_ 480
#define BT_ (B_*T_)          // 15360
#define STAT_CHUNKS 480
#define ROWS_PER_CHUNK (BT_/STAT_CHUNKS)   // 32

// ---------------- scratch (static device arrays; no allocations) ----------------
__device__ float g_f2[B_*C_*T_];        // [b][c][t]   2 MB
__device__ float g_tmp[B_*C_*T_];       // [b][c][t]   2 MB
__device__ float g_logits[(size_t)B_*T_*T_];  // [b][t][s]  28 MB
__device__ float g_out2[(size_t)B_*T_*T_];    // [b][t][u]  28 MB
__device__ float g_psum[STAT_CHUNKS*T_];
__device__ float g_psumsq[STAT_CHUNKS*T_];
__device__ float g_scale[T_];
__device__ float g_shift[T_];

// ================================================================================
// K1: single pass over seq  ->  f2[b,c,t] = sum_n w2[n]*seq[b,c,n,t]
//                               tmp[b,c,t] = sum_n w[n,c] * (sum_c' w1[c']*seq[b,c',n,t])
// ================================================================================
__global__ __launch_bounds__(256, 2)
void k1_fused(const float* __restrict__ seq, const float* __restrict__ w1,
              const float* __restrict__ w2, const float* __restrict__ w)
{
    __shared__ float sbuf[32*8*32];
    __shared__ float w1s[32];
    __shared__ float w2s[N_];

    const int tid = threadIdx.x;
    const int tt  = tid & 31;
    const int ng  = tid >> 5;
    const int tc  = blockIdx.x;
    const int b   = blockIdx.y;
    const int t   = tc*32 + tt;

    if (tid < 32) w1s[tid] = w1[tid];
    for (int i = tid; i < N_; i += 256) w2s[i] = w2[i];

    float f2loc[32], tmploc[32];
    #pragma unroll
    for (int c = 0; c < 32; ++c) { f2loc[c] = 0.f; tmploc[c] = 0.f; }

    const float* seqb = seq + (size_t)b*C_*N_*T_ + t;

    for (int ph = 0; ph < 4; ++ph) {
        __syncthreads();
        for (int i = tid; i < 128*32; i += 256)
            sbuf[i] = w[ph*128*32 + i];
        __syncthreads();

        const int nbase = ph*128 + ng*16;
        for (int j = 0; j < 16; ++j) {
            const int n = nbase + j;
            const float* p = seqb + (size_t)n*T_;
            const float w2n = w2s[n];
            float f1acc = 0.f;
            #pragma unroll
            for (int c = 0; c < 32; ++c) {
                float v = p[(size_t)c*N_*T_];
                f1acc    = fmaf(w1s[c], v, f1acc);
                f2loc[c] = fmaf(w2n,    v, f2loc[c]);
            }
            const float* wr = &sbuf[(n - ph*128)*32];
            #pragma unroll
            for (int c = 0; c < 32; ++c)
                tmploc[c] = fmaf(wr[c], f1acc, tmploc[c]);
        }
    }

    __syncthreads();
    #pragma unroll
    for (int c = 0; c < 32; ++c) sbuf[c*256 + ng*32 + tt] = f2loc[c];
    __syncthreads();
    #pragma unroll
    for (int k = 0; k < 4; ++k) {
        const int o = tid + k*256;
        const int c = o >> 5, t2 = o & 31;
        float s = 0.f;
        #pragma unroll
        for (int g = 0; g < 8; ++g) s += sbuf[c*256 + g*32 + t2];
        g_f2[((size_t)b*C_ + c)*T_ + tc*32 + t2] = s;
    }
    __syncthreads();
    #pragma unroll
    for (int c = 0; c < 32; ++c) sbuf[c*256 + ng*32 + tt] = tmploc[c];
    __syncthreads();
    #pragma unroll
    for (int k = 0; k < 4; ++k) {
        const int o = tid + k*256;
        const int c = o >> 5, t2 = o & 31;
        float s = 0.f;
        #pragma unroll
        for (int g = 0; g < 8; ++g) s += sbuf[c*256 + g*32 + t2];
        g_tmp[((size_t)b*C_ + c)*T_ + tc*32 + t2] = s;
    }
}

// ================================================================================
// K2: logits[b,t,s] = sigmoid( sum_c tmp[b,c,t]*f2[b,c,s] + bmat[t,s] )
// ================================================================================
__global__ __launch_bounds__(480)
void k2_logits(const float* __restrict__ bmat)
{
    __shared__ float tmps[32*32];
    const int s  = threadIdx.x;
    const int tc = blockIdx.x;
    const int b  = blockIdx.y;

    for (int i = s; i < 1024; i += 480) {
        const int c = i >> 5, tt = i & 31;
        tmps[i] = g_tmp[((size_t)b*C_ + c)*T_ + tc*32 + tt];
    }
    __syncthreads();

    float f2r[32];
    #pragma unroll
    for (int c = 0; c < 32; ++c) f2r[c] = g_f2[((size_t)b*C_ + c)*T_ + s];

    for (int tg = 0; tg < 8; ++tg) {
        const int t0 = tc*32 + tg*4;
        float a0 = bmat[(size_t)(t0+0)*T_ + s];
        float a1 = bmat[(size_t)(t0+1)*T_ + s];
        float a2 = bmat[(size_t)(t0+2)*T_ + s];
        float a3 = bmat[(size_t)(t0+3)*T_ + s];
        #pragma unroll
        for (int c = 0; c < 32; ++c) {
            float4 tv = *reinterpret_cast<const float4*>(&tmps[c*32 + tg*4]);
            const float f = f2r[c];
            a0 = fmaf(tv.x, f, a0);
            a1 = fmaf(tv.y, f, a1);
            a2 = fmaf(tv.z, f, a2);
            a3 = fmaf(tv.w, f, a3);
        }
        const size_t o = ((size_t)b*T_ + t0)*T_ + s;
        g_logits[o        ] = 1.f/(1.f + __expf(-a0));
        g_logits[o +   T_ ] = 1.f/(1.f + __expf(-a1));
        g_logits[o + 2*T_ ] = 1.f/(1.f + __expf(-a2));
        g_logits[o + 3*T_ ] = 1.f/(1.f + __expf(-a3));
    }
}

// ================================================================================
// K3: out2[b,t,u] = sum_s v[t,s] * logits[b,s,u]
// Tensor-core split-TF32: out = Ah*Bh + Ah*Bl + Al*Bh  (mma.sync m16n8k8 tf32)
// CTA 96x96, 4 warps (2x2) of 48x48 warp tiles. K chunks of 24, cp.async 2-stage.
// ================================================================================
__device__ __forceinline__ float to_tf32(float x)
{
    float r;
    asm("cvt.rna.tf32.f32 %0, %1;" : "=f"(r) : "f"(x));
    return r;
}

__device__ __forceinline__ void mma_tf32(float* d, const unsigned* a, const unsigned* b)
{
    asm volatile(
        "mma.sync.aligned.m16n8k8.row.col.f32.tf32.tf32.f32 "
        "{%0,%1,%2,%3}, {%4,%5,%6,%7}, {%8,%9}, {%0,%1,%2,%3};"
        : "+f"(d[0]), "+f"(d[1]), "+f"(d[2]), "+f"(d[3])
        : "r"(a[0]), "r"(a[1]), "r"(a[2]), "r"(a[3]), "r"(b[0]), "r"(b[1]));
}

__device__ __forceinline__ void cpasync16(void* smem_dst, const void* gsrc)
{
    unsigned s = (unsigned)__cvta_generic_to_shared(smem_dst);
    asm volatile("cp.async.cg.shared.global [%0], [%1], 16;\n" :: "r"(s), "l"(gsrc));
}

#define KC3 24
#define NCHUNK (T_/KC3)   // 20

__global__ __launch_bounds__(128, 3)
void k3_gemm_tc(const float* __restrict__ v)
{
    __shared__ float As[2][96][28];    // raw v tile  [m][k], stride 28 (conflict-free frags)
    __shared__ float Bs[2][KC3][100];  // raw logits  [k][n], stride 100

    const int tid  = threadIdx.x;
    const int lane = tid & 31;
    const int wid  = tid >> 5;
    const int g    = lane >> 2;      // 0..7
    const int tg   = lane & 3;       // 0..3
    const int wm   = wid >> 1;       // 0..1
    const int wn   = wid & 1;        // 0..1
    const int u0   = blockIdx.x * 96;
    const int t0   = blockIdx.y * 96;
    const int b    = blockIdx.z;
    const float* Lb = g_logits + (size_t)b*T_*T_;

    float acc[3][6][4];
    #pragma unroll
    for (int i = 0; i < 3; ++i)
        #pragma unroll
        for (int j = 0; j < 6; ++j)
            #pragma unroll
            for (int q = 0; q < 4; ++q) acc[i][j][q] = 0.f;

    // ---- async chunk loader: A = 96x24 (576 f4), B = 24x96 (576 f4) ----
    auto load_chunk = [&](int ch, int stg) {
        const int k0 = ch * KC3;
        #pragma unroll
        for (int r = 0; r < 5; ++r) {
            const int idx = tid + r*128;
            if (r < 4 || tid < 64) {
                const int row = idx / 6, c4 = idx % 6;
                cpasync16(&As[stg][row][c4*4],
                          v + (size_t)(t0 + row)*T_ + k0 + c4*4);
            }
        }
        #pragma unroll
        for (int r = 0; r < 5; ++r) {
            const int idx = tid + r*128;
            if (r < 4 || tid < 64) {
                const int row = idx / 24, c4 = idx % 24;
                cpasync16(&Bs[stg][row][c4*4],
                          Lb + (size_t)(k0 + row)*T_ + u0 + c4*4);
            }
        }
        asm volatile("cp.async.commit_group;\n" ::);
    };

    load_chunk(0, 0);

    for (int ch = 0; ch < NCHUNK; ++ch) {
        const int stg = ch & 1;
        if (ch + 1 < NCHUNK) {
            load_chunk(ch + 1, stg ^ 1);
            asm volatile("cp.async.wait_group 1;\n" ::);
        } else {
            asm volatile("cp.async.wait_group 0;\n" ::);
        }
        __syncthreads();

        #pragma unroll
        for (int kk = 0; kk < 3; ++kk) {
            const int kc = kk * 8;

            unsigned ah[3][4], al[3][4];
            #pragma unroll
            for (int i = 0; i < 3; ++i) {
                const int r0 = wm*48 + i*16 + g;
                const float x0 = As[stg][r0    ][kc + tg];
                const float x1 = As[stg][r0 + 8][kc + tg];
                const float x2 = As[stg][r0    ][kc + tg + 4];
                const float x3 = As[stg][r0 + 8][kc + tg + 4];
                float h;
                h = to_tf32(x0); ah[i][0] = __float_as_uint(h); al[i][0] = __float_as_uint(to_tf32(x0 - h));
                h = to_tf32(x1); ah[i][1] = __float_as_uint(h); al[i][1] = __float_as_uint(to_tf32(x1 - h));
                h = to_tf32(x2); ah[i][2] = __float_as_uint(h); al[i][2] = __float_as_uint(to_tf32(x2 - h));
                h = to_tf32(x3); ah[i][3] = __float_as_uint(h); al[i][3] = __float_as_uint(to_tf32(x3 - h));
            }

            unsigned bh[6][2], bl[6][2];
            #pragma unroll
            for (int j = 0; j < 6; ++j) {
                const int n = wn*48 + j*8 + g;
                const float y0 = Bs[stg][kc + tg    ][n];
                const float y1 = Bs[stg][kc + tg + 4][n];
                float h;
                h = to_tf32(y0); bh[j][0] = __float_as_uint(h); bl[j][0] = __float_as_uint(to_tf32(y0 - h));
                h = to_tf32(y1); bh[j][1] = __float_as_uint(h); bl[j][1] = __float_as_uint(to_tf32(y1 - h));
            }

            #pragma unroll
            for (int i = 0; i < 3; ++i)
                #pragma unroll
                for (int j = 0; j < 6; ++j) {
                    mma_tf32(acc[i][j], ah[i], bh[j]);
                    mma_tf32(acc[i][j], ah[i], bl[j]);
                    mma_tf32(acc[i][j], al[i], bh[j]);
                }
        }
        __syncthreads();
    }

    // ---- epilogue ----
    float* ob = g_out2 + (size_t)b*T_*T_;
    #pragma unroll
    for (int i = 0; i < 3; ++i) {
        const int row0 = t0 + wm*48 + i*16 + g;
        #pragma unroll
        for (int j = 0; j < 6; ++j) {
            const int col = u0 + wn*48 + j*8 + tg*2;
            float2 p0; p0.x = acc[i][j][0]; p0.y = acc[i][j][1];
            float2 p1; p1.x = acc[i][j][2]; p1.y = acc[i][j][3];
            *reinterpret_cast<float2*>(&ob[(size_t)row0*T_ + col])       = p0;
            *reinterpret_cast<float2*>(&ob[(size_t)(row0+8)*T_ + col])   = p1;
        }
    }
}

// ================================================================================
// K4/K5: BatchNorm batch stats over (b,t) per u — deterministic two-stage.
// ================================================================================
__global__ __launch_bounds__(480)
void k4_stats()
{
    const int u  = threadIdx.x;
    const int ch = blockIdx.x;
    const float* base = g_out2 + (size_t)ch*ROWS_PER_CHUNK*T_ + u;
    float s = 0.f, q = 0.f;
    #pragma unroll 8
    for (int r = 0; r < ROWS_PER_CHUNK; ++r) {
        const float x = base[(size_t)r*T_];
        s += x;
        q = fmaf(x, x, q);
    }
    g_psum  [ch*T_ + u] = s;
    g_psumsq[ch*T_ + u] = q;
}

__global__ __launch_bounds__(128)
void k5_final(const float* __restrict__ gamma, const float* __restrict__ beta)
{
    const int u = blockIdx.x*128 + threadIdx.x;
    if (u >= T_) return;
    float s = 0.f, q = 0.f;
    for (int ch = 0; ch < STAT_CHUNKS; ++ch) { s += g_psum[ch*T_+u]; q += g_psumsq[ch*T_+u]; }
    const float mean = s * (1.f/(float)BT_);
    const float var  = q * (1.f/(float)BT_) - mean*mean;
    const float sc   = gamma[u] * rsqrtf(var + 1e-5f);
    g_scale[u] = sc;
    g_shift[u] = beta[u] - mean*sc;
}

// ================================================================================
// K6: out[b,t,u] = softmax_u( out2*scale + shift + mask[t,u] )
// ================================================================================
__global__ __launch_bounds__(512)
void k6_softmax(const float* __restrict__ mask, float* __restrict__ out)
{
    __shared__ float red[16];
    const int row = blockIdx.x;
    const int t   = row % T_;
    const int tid = threadIdx.x;

    float e = 0.f;
    if (tid < T_) {
        const float x = g_out2[(size_t)row*T_ + tid] * g_scale[tid] + g_shift[tid]
                      + mask[(size_t)t*T_ + tid];
        e = __expf(x);
    }
    float s = e;
    #pragma unroll
    for (int o = 16; o > 0; o >>= 1) s += __shfl_xor_sync(0xffffffffu, s, o);
    if ((tid & 31) == 0) red[tid >> 5] = s;
    __syncthreads();
    if (tid < 32) {
        float v2 = (tid < 16) ? red[tid] : 0.f;
        #pragma unroll
        for (int o = 8; o > 0; o >>= 1) v2 += __shfl_xor_sync(0xffffffffu, v2, o);
        if (tid == 0) red[0] = v2;
    }
    __syncthreads();
    const float inv = 1.f / red[0];
    if (tid < T_) out[(size_t)row*T_ + tid] = e * inv;
}

// ================================================================================
extern "C" void kernel_launch(void* const* d_in, const int* in_sizes, int n_in,
                              void* d_out, int out_size)
{
    const float* seq   = (const float*)d_in[0];
    const float* w1    = (const float*)d_in[1];
    const float* w2    = (const float*)d_in[2];
    const float* w     = (const float*)d_in[3];
    const float* bmat  = (const float*)d_in[4];
    const float* v     = (const float*)d_in[5];
    const float* gamma = (const float*)d_in[6];
    const float* beta  = (const float*)d_in[7];
    const float* mask  = (const float*)d_in[8];
    float* out = (float*)d_out;

    k1_fused  <<<dim3(15, 32), 256>>>(seq, w1, w2, w);
    k2_logits <<<dim3(15, 32), 480>>>(bmat);
    k3_gemm_tc<<<dim3(5, 5, 32), 128>>>(v);
    k4_stats  <<<STAT_CHUNKS, 480>>>();
    k5_final  <<<4, 128>>>(gamma, beta);
    k6_softmax<<<BT_, 512>>>(mask, out);
}

// round 4
// speedup vs baseline: 1.2506x; 1.1083x over previous
#include <cuda_runtime.h>
#include <cuda_fp16.h>
#include <cstddef>
#include <cstdint>

#define B_ 32
#define C_ 32
#define N_ 512
#define T_ 480
#define BT_ (B_*T_)          // 15360
#define STAT_CHUNKS 480
#define ROWS_PER_CHUNK (BT_/STAT_CHUNKS)   // 32

// ---------------- scratch (static device arrays; no allocations) ----------------
__device__ float g_f2[B_*C_*T_];
__device__ float g_tmp[B_*C_*T_];
__device__ float g_out2[(size_t)B_*T_*T_];          // [b][t][u] f32   28 MB
__device__ __half g_vhi[512*512];                   // v split, zero-padded
__device__ __half g_vlo[512*512];
__device__ __half g_Lhi[(size_t)B_*T_*512];         // logits split [b][s][u], u-stride 512
__device__ __half g_Llo[(size_t)B_*T_*512];
__device__ float g_psum[STAT_CHUNKS*T_];
__device__ float g_psumsq[STAT_CHUNKS*T_];
__device__ float g_scale[T_];
__device__ float g_shift[T_];

// ================================================================================
// K1: single pass over seq -> f2 and tmp (DRAM-bound, unchanged)
// ================================================================================
__global__ __launch_bounds__(256, 2)
void k1_fused(const float* __restrict__ seq, const float* __restrict__ w1,
              const float* __restrict__ w2, const float* __restrict__ w)
{
    __shared__ float sbuf[32*8*32];
    __shared__ float w1s[32];
    __shared__ float w2s[N_];

    const int tid = threadIdx.x;
    const int tt  = tid & 31;
    const int ng  = tid >> 5;
    const int tc  = blockIdx.x;
    const int b   = blockIdx.y;
    const int t   = tc*32 + tt;

    if (tid < 32) w1s[tid] = w1[tid];
    for (int i = tid; i < N_; i += 256) w2s[i] = w2[i];

    float f2loc[32], tmploc[32];
    #pragma unroll
    for (int c = 0; c < 32; ++c) { f2loc[c] = 0.f; tmploc[c] = 0.f; }

    const float* seqb = seq + (size_t)b*C_*N_*T_ + t;

    for (int ph = 0; ph < 4; ++ph) {
        __syncthreads();
        for (int i = tid; i < 128*32; i += 256)
            sbuf[i] = w[ph*128*32 + i];
        __syncthreads();

        const int nbase = ph*128 + ng*16;
        for (int j = 0; j < 16; ++j) {
            const int n = nbase + j;
            const float* p = seqb + (size_t)n*T_;
            const float w2n = w2s[n];
            float f1acc = 0.f;
            #pragma unroll
            for (int c = 0; c < 32; ++c) {
                float v = p[(size_t)c*N_*T_];
                f1acc    = fmaf(w1s[c], v, f1acc);
                f2loc[c] = fmaf(w2n,    v, f2loc[c]);
            }
            const float* wr = &sbuf[(n - ph*128)*32];
            #pragma unroll
            for (int c = 0; c < 32; ++c)
                tmploc[c] = fmaf(wr[c], f1acc, tmploc[c]);
        }
    }

    __syncthreads();
    #pragma unroll
    for (int c = 0; c < 32; ++c) sbuf[c*256 + ng*32 + tt] = f2loc[c];
    __syncthreads();
    #pragma unroll
    for (int k = 0; k < 4; ++k) {
        const int o = tid + k*256;
        const int c = o >> 5, t2 = o & 31;
        float s = 0.f;
        #pragma unroll
        for (int g = 0; g < 8; ++g) s += sbuf[c*256 + g*32 + t2];
        g_f2[((size_t)b*C_ + c)*T_ + tc*32 + t2] = s;
    }
    __syncthreads();
    #pragma unroll
    for (int c = 0; c < 32; ++c) sbuf[c*256 + ng*32 + tt] = tmploc[c];
    __syncthreads();
    #pragma unroll
    for (int k = 0; k < 4; ++k) {
        const int o = tid + k*256;
        const int c = o >> 5, t2 = o & 31;
        float s = 0.f;
        #pragma unroll
        for (int g = 0; g < 8; ++g) s += sbuf[c*256 + g*32 + t2];
        g_tmp[((size_t)b*C_ + c)*T_ + tc*32 + t2] = s;
    }
}

// ================================================================================
// k0: split v into fp16 hi/lo (padded 512 stride; pad rows/cols stay zero)
// ================================================================================
__global__ __launch_bounds__(256)
void k0_splitv(const float* __restrict__ v)
{
    const int i = blockIdx.x*256 + threadIdx.x;
    if (i >= T_*T_) return;
    const int t = i / T_, s = i - t*T_;
    const float x = v[i];
    const __half hi = __float2half_rn(x);
    const __half lo = __float2half_rn(x - __half2float(hi));
    g_vhi[t*512 + s] = hi;
    g_vlo[t*512 + s] = lo;
}

// ================================================================================
// K2: logits[b,i,j] = sigmoid( sum_c tmp[b,c,i]*f2[b,c,j] + bmat[i,j] )
//     emitted directly as fp16 hi/lo, row stride 512 (cols 480..511 stay zero).
// ================================================================================
__global__ __launch_bounds__(480)
void k2_logits(const float* __restrict__ bmat)
{
    __shared__ float tmps[32*32];
    const int s  = threadIdx.x;
    const int tc = blockIdx.x;
    const int b  = blockIdx.y;

    for (int i = s; i < 1024; i += 480) {
        const int c = i >> 5, tt = i & 31;
        tmps[i] = g_tmp[((size_t)b*C_ + c)*T_ + tc*32 + tt];
    }
    __syncthreads();

    float f2r[32];
    #pragma unroll
    for (int c = 0; c < 32; ++c) f2r[c] = g_f2[((size_t)b*C_ + c)*T_ + s];

    for (int tg = 0; tg < 8; ++tg) {
        const int t0 = tc*32 + tg*4;
        float a0 = bmat[(size_t)(t0+0)*T_ + s];
        float a1 = bmat[(size_t)(t0+1)*T_ + s];
        float a2 = bmat[(size_t)(t0+2)*T_ + s];
        float a3 = bmat[(size_t)(t0+3)*T_ + s];
        #pragma unroll
        for (int c = 0; c < 32; ++c) {
            float4 tv = *reinterpret_cast<const float4*>(&tmps[c*32 + tg*4]);
            const float f = f2r[c];
            a0 = fmaf(tv.x, f, a0);
            a1 = fmaf(tv.y, f, a1);
            a2 = fmaf(tv.z, f, a2);
            a3 = fmaf(tv.w, f, a3);
        }
        const size_t o = ((size_t)b*T_ + t0)*512 + s;
        float xs[4];
        xs[0] = 1.f/(1.f + __expf(-a0));
        xs[1] = 1.f/(1.f + __expf(-a1));
        xs[2] = 1.f/(1.f + __expf(-a2));
        xs[3] = 1.f/(1.f + __expf(-a3));
        #pragma unroll
        for (int r = 0; r < 4; ++r) {
            const __half hi = __float2half_rn(xs[r]);
            const __half lo = __float2half_rn(xs[r] - __half2float(hi));
            g_Lhi[o + (size_t)r*512] = hi;
            g_Llo[o + (size_t)r*512] = lo;
        }
    }
}

// ================================================================================
// K3: out2[b,t,u] = sum_s v[t,s]*L[b,s,u]   via fp16-split mma.m16n8k16
// CTA 128x128, 8 warps (2x4) of 64x32 warp tiles. KC=32, cp.async double buffer.
// D = Ah*Bh + Ah*Bl + Al*Bh  (fp32 accum).
// ================================================================================
#define KC 32
#define NKCH (T_/KC)            // 15
#define A_STRIDE 40             // halves per A row (conflict-free)
#define B_STRIDE 136            // halves per B row (conflict-free for trans)
#define A_BUF_B (128*A_STRIDE*2)   // 10240 bytes per precision
#define B_BUF_B (KC*B_STRIDE*2)    // 8704 bytes per precision
#define STAGE_B (2*A_BUF_B + 2*B_BUF_B)   // 37888
#define SMEM_K3 (2*STAGE_B)               // 75776

__device__ __forceinline__ void cpasync16(uint32_t dst, const void* src) {
    asm volatile("cp.async.cg.shared.global [%0], [%1], 16;\n" :: "r"(dst), "l"(src));
}
__device__ __forceinline__ void ldsm_x4(uint32_t* r, uint32_t addr) {
    asm volatile("ldmatrix.sync.aligned.m8n8.x4.shared.b16 {%0,%1,%2,%3}, [%4];"
                 : "=r"(r[0]), "=r"(r[1]), "=r"(r[2]), "=r"(r[3]) : "r"(addr));
}
__device__ __forceinline__ void ldsm_x4t(uint32_t* r, uint32_t addr) {
    asm volatile("ldmatrix.sync.aligned.m8n8.x4.trans.shared.b16 {%0,%1,%2,%3}, [%4];"
                 : "=r"(r[0]), "=r"(r[1]), "=r"(r[2]), "=r"(r[3]) : "r"(addr));
}
__device__ __forceinline__ void mma16816(float* d, const uint32_t* a, const uint32_t* b) {
    asm volatile(
        "mma.sync.aligned.m16n8k16.row.col.f32.f16.f16.f32 "
        "{%0,%1,%2,%3}, {%4,%5,%6,%7}, {%8,%9}, {%0,%1,%2,%3};"
        : "+f"(d[0]), "+f"(d[1]), "+f"(d[2]), "+f"(d[3])
        : "r"(a[0]), "r"(a[1]), "r"(a[2]), "r"(a[3]), "r"(b[0]), "r"(b[1]));
}

__global__ __launch_bounds__(256, 1)
void k3_fp16()
{
    extern __shared__ char smem[];
    const uint32_t smb = (uint32_t)__cvta_generic_to_shared(smem);

    const int tid  = threadIdx.x;
    const int lane = tid & 31;
    const int wid  = tid >> 5;
    const int wm   = wid >> 2;            // 0..1
    const int wn   = wid & 3;             // 0..3
    const int u0   = blockIdx.x * 128;
    const int t0   = blockIdx.y * 128;
    const int b    = blockIdx.z;

    float acc[4][4][4];
    #pragma unroll
    for (int i = 0; i < 4; ++i)
        #pragma unroll
        for (int j = 0; j < 4; ++j)
            #pragma unroll
            for (int q = 0; q < 4; ++q) acc[i][j][q] = 0.f;

    // per-thread cp.async coords (constant across chunks)
    const int arow = tid >> 1;                 // A: 128 rows, 2 thr/row
    const int aq   = (tid & 1) * 2;            // two 16B pieces per thread per half-row... (4 pieces/row)
    const int brow = tid >> 3;                 // B: 32 rows, 8 thr/row
    const int bq   = (tid & 7) * 2;            // 16 pieces/row, 2 per thread

    auto load_chunk = [&](int ch, int st) {
        const int k0e = ch * KC;
        const uint32_t abase = smb + st*STAGE_B;
        const uint32_t bbase = abase + 2*A_BUF_B;
        #pragma unroll
        for (int p = 0; p < 2; ++p) {
            const __half* srcA = (p ? g_vlo : g_vhi) + (size_t)(t0 + arow)*512 + k0e;
            const uint32_t adst = abase + p*A_BUF_B + (arow*A_STRIDE)*2;
            cpasync16(adst + aq*16,        srcA + aq*8);
            cpasync16(adst + (aq+1)*16,    srcA + (aq+1)*8);
            const __half* srcB = (p ? g_Llo : g_Lhi) + ((size_t)b*T_ + k0e + brow)*512 + u0;
            const uint32_t bdst = bbase + p*B_BUF_B + (brow*B_STRIDE)*2;
            cpasync16(bdst + bq*16,        srcB + bq*8);
            cpasync16(bdst + (bq+1)*16,    srcB + (bq+1)*8);
        }
        asm volatile("cp.async.commit_group;\n" ::);
    };

    load_chunk(0, 0);

    for (int ch = 0; ch < NKCH; ++ch) {
        const int st = ch & 1;
        if (ch + 1 < NKCH) {
            load_chunk(ch + 1, st ^ 1);
            asm volatile("cp.async.wait_group 1;\n" ::);
        } else {
            asm volatile("cp.async.wait_group 0;\n" ::);
        }
        __syncthreads();

        const uint32_t abase = smb + st*STAGE_B;
        const uint32_t bbase = abase + 2*A_BUF_B;

        #pragma unroll
        for (int kk = 0; kk < 2; ++kk) {
            const int kc = kk * 16;
            // ---- B fragments: 2 x ldmatrix.x4.trans per precision ----
            uint32_t bh[4][2], bl[4][2];
            {
                const int r  = lane & 7;
                const int tb = lane >> 3;
                const int rowk = kc + (tb & 1)*8 + r;
                #pragma unroll
                for (int jj = 0; jj < 2; ++jj) {
                    const int coln = wn*32 + jj*16 + (tb >> 1)*8;
                    const uint32_t ba = (uint32_t)(rowk*B_STRIDE + coln)*2;
                    uint32_t rh[4], rl[4];
                    ldsm_x4t(rh, bbase + ba);
                    ldsm_x4t(rl, bbase + B_BUF_B + ba);
                    bh[jj*2  ][0] = rh[0]; bh[jj*2  ][1] = rh[1];
                    bh[jj*2+1][0] = rh[2]; bh[jj*2+1][1] = rh[3];
                    bl[jj*2  ][0] = rl[0]; bl[jj*2  ][1] = rl[1];
                    bl[jj*2+1][0] = rl[2]; bl[jj*2+1][1] = rl[3];
                }
            }
            // ---- A fragments: 4 x ldmatrix.x4 per precision ----
            uint32_t ah[4][4], al[4][4];
            {
                const int r  = lane & 7;
                const int tb = lane >> 3;
                const int rr = (tb & 1)*8 + r;
                const int cc = kc + (tb >> 1)*8;
                #pragma unroll
                for (int i = 0; i < 4; ++i) {
                    const int row = wm*64 + i*16 + rr;
                    const uint32_t aa = (uint32_t)(row*A_STRIDE + cc)*2;
                    ldsm_x4(ah[i], abase + aa);
                    ldsm_x4(al[i], abase + A_BUF_B + aa);
                }
            }
            // ---- 48 MMAs ----
            #pragma unroll
            for (int i = 0; i < 4; ++i)
                #pragma unroll
                for (int j = 0; j < 4; ++j) {
                    mma16816(acc[i][j], ah[i], bh[j]);
                    mma16816(acc[i][j], ah[i], bl[j]);
                    mma16816(acc[i][j], al[i], bh[j]);
                }
        }
        __syncthreads();
    }

    // ---- epilogue: direct float2 stores with bounds guards ----
    float* ob = g_out2 + (size_t)b*T_*T_;
    #pragma unroll
    for (int i = 0; i < 4; ++i) {
        const int r0 = t0 + wm*64 + i*16 + (lane >> 2);
        #pragma unroll
        for (int j = 0; j < 4; ++j) {
            const int cN = u0 + wn*32 + j*8 + (lane & 3)*2;
            if (cN < T_) {
                if (r0 < T_) {
                    float2 p; p.x = acc[i][j][0]; p.y = acc[i][j][1];
                    *reinterpret_cast<float2*>(&ob[(size_t)r0*T_ + cN]) = p;
                }
                if (r0 + 8 < T_) {
                    float2 p; p.x = acc[i][j][2]; p.y = acc[i][j][3];
                    *reinterpret_cast<float2*>(&ob[(size_t)(r0+8)*T_ + cN]) = p;
                }
            }
        }
    }
}

// ================================================================================
// K4/K5: BatchNorm stats (unchanged)
// ================================================================================
__global__ __launch_bounds__(480)
void k4_stats()
{
    const int u  = threadIdx.x;
    const int ch = blockIdx.x;
    const float* base = g_out2 + (size_t)ch*ROWS_PER_CHUNK*T_ + u;
    float s = 0.f, q = 0.f;
    #pragma unroll 8
    for (int r = 0; r < ROWS_PER_CHUNK; ++r) {
        const float x = base[(size_t)r*T_];
        s += x;
        q = fmaf(x, x, q);
    }
    g_psum  [ch*T_ + u] = s;
    g_psumsq[ch*T_ + u] = q;
}

__global__ __launch_bounds__(128)
void k5_final(const float* __restrict__ gamma, const float* __restrict__ beta)
{
    const int u = blockIdx.x*128 + threadIdx.x;
    if (u >= T_) return;
    float s = 0.f, q = 0.f;
    for (int ch = 0; ch < STAT_CHUNKS; ++ch) { s += g_psum[ch*T_+u]; q += g_psumsq[ch*T_+u]; }
    const float mean = s * (1.f/(float)BT_);
    const float var  = q * (1.f/(float)BT_) - mean*mean;
    const float sc   = gamma[u] * rsqrtf(var + 1e-5f);
    g_scale[u] = sc;
    g_shift[u] = beta[u] - mean*sc;
}

// ================================================================================
// K6: masked softmax (unchanged)
// ================================================================================
__global__ __launch_bounds__(512)
void k6_softmax(const float* __restrict__ mask, float* __restrict__ out)
{
    __shared__ float red[16];
    const int row = blockIdx.x;
    const int t   = row % T_;
    const int tid = threadIdx.x;

    float e = 0.f;
    if (tid < T_) {
        const float x = g_out2[(size_t)row*T_ + tid] * g_scale[tid] + g_shift[tid]
                      + mask[(size_t)t*T_ + tid];
        e = __expf(x);
    }
    float s = e;
    #pragma unroll
    for (int o = 16; o > 0; o >>= 1) s += __shfl_xor_sync(0xffffffffu, s, o);
    if ((tid & 31) == 0) red[tid >> 5] = s;
    __syncthreads();
    if (tid < 32) {
        float v2 = (tid < 16) ? red[tid] : 0.f;
        #pragma unroll
        for (int o = 8; o > 0; o >>= 1) v2 += __shfl_xor_sync(0xffffffffu, v2, o);
        if (tid == 0) red[0] = v2;
    }
    __syncthreads();
    const float inv = 1.f / red[0];
    if (tid < T_) out[(size_t)row*T_ + tid] = e * inv;
}

// ================================================================================
extern "C" void kernel_launch(void* const* d_in, const int* in_sizes, int n_in,
                              void* d_out, int out_size)
{
    const float* seq   = (const float*)d_in[0];
    const float* w1    = (const float*)d_in[1];
    const float* w2    = (const float*)d_in[2];
    const float* w     = (const float*)d_in[3];
    const float* bmat  = (const float*)d_in[4];
    const float* v     = (const float*)d_in[5];
    const float* gamma = (const float*)d_in[6];
    const float* beta  = (const float*)d_in[7];
    const float* mask  = (const float*)d_in[8];
    float* out = (float*)d_out;

    cudaFuncSetAttribute(k3_fp16, cudaFuncAttributeMaxDynamicSharedMemorySize, SMEM_K3);

    k0_splitv <<<(T_*T_ + 255)/256, 256>>>(v);
    k1_fused  <<<dim3(15, 32), 256>>>(seq, w1, w2, w);
    k2_logits <<<dim3(15, 32), 480>>>(bmat);
    k3_fp16   <<<dim3(4, 4, 32), 256, SMEM_K3>>>();
    k4_stats  <<<STAT_CHUNKS, 480>>>();
    k5_final  <<<4, 128>>>(gamma, beta);
    k6_softmax<<<BT_, 512>>>(mask, out);
}

// round 5
// speedup vs baseline: 1.3435x; 1.0743x over previous
#include <cuda_runtime.h>
#include <cuda_fp16.h>
#include <cstddef>
#include <cstdint>

#define B_ 32
#define C_ 32
#define N_ 512
#define T_ 480
#define BT_ (B_*T_)          // 15360
#define STAT_CHUNKS 480
#define ROWS_PER_CHUNK (BT_/STAT_CHUNKS)   // 32

// ---------------- scratch (static device arrays; no allocations) ----------------
__device__ float g_f2[B_*C_*T_];
__device__ float g_tmp[B_*C_*T_];
__device__ float g_out2[(size_t)B_*T_*T_];          // [b][t][u] f32   28 MB
__device__ __half g_vhi[512*512];                   // v split, zero-padded
__device__ __half g_vlo[512*512];
__device__ __half g_Lhi[(size_t)B_*T_*512];         // logits split [b][s][u], u-stride 512
__device__ __half g_Llo[(size_t)B_*T_*512];
__device__ float g_psum[STAT_CHUNKS*T_];
__device__ float g_psumsq[STAT_CHUNKS*T_];
__device__ float g_scale[T_];
__device__ float g_shift[T_];

// ================================================================================
// K1: single pass over seq -> f2 and tmp.
// Lane = (t-pair tl, c-half ch): 16 c per lane (float2 over t), f1 combined
// across halves via shfl_xor(16). ~108 regs -> no spills at 2 CTAs/SM.
// ================================================================================
__global__ __launch_bounds__(256, 2)
void k1_fused(const float* __restrict__ seq, const float* __restrict__ w1,
              const float* __restrict__ w2, const float* __restrict__ w)
{
    __shared__ float sbuf[8192];   // 32KB: w tile (4096) during phases; reduction (8192) at end
    __shared__ float w1sh[32];
    __shared__ float w2s[N_];

    const int tid  = threadIdx.x;
    const int lane = tid & 31;
    const int ng   = tid >> 5;     // warp 0..7 = n-group
    const int tl   = lane & 15;    // t-pair index
    const int ch   = lane >> 4;    // c half 0/1
    const int tc   = blockIdx.x;   // 0..14
    const int b    = blockIdx.y;   // 0..31

    if (tid < 32) w1sh[tid] = w1[tid];
    for (int i = tid; i < N_; i += 256) w2s[i] = w2[i];

    float2 f2loc[16], tmploc[16];
    #pragma unroll
    for (int c = 0; c < 16; ++c) {
        f2loc[c].x = 0.f; f2loc[c].y = 0.f;
        tmploc[c].x = 0.f; tmploc[c].y = 0.f;
    }

    // float2 view: element (c,n,t): float2 idx = c*122880 + n*240 + tc*16 + tl
    const float2* seqb = reinterpret_cast<const float2*>(seq + (size_t)b*C_*N_*T_)
                         + tc*16 + tl + (size_t)ch*16*122880;

    for (int ph = 0; ph < 4; ++ph) {
        __syncthreads();                                   // protect sbuf (and w1sh/w2s on ph=0)
        for (int i = tid; i < 128*32; i += 256)
            sbuf[i] = w[ph*128*32 + i];
        __syncthreads();

        const int nbase = ph*128 + ng*16;
        for (int j = 0; j < 16; ++j) {
            const int n = nbase + j;
            const float2* p = seqb + (size_t)n*240;
            const float w2n = w2s[n];
            float f1x = 0.f, f1y = 0.f;
            #pragma unroll
            for (int c = 0; c < 16; ++c) {
                const float2 x = p[(size_t)c*122880];
                const float w1c = w1sh[ch*16 + c];
                f1x = fmaf(w1c, x.x, f1x);
                f1y = fmaf(w1c, x.y, f1y);
                f2loc[c].x = fmaf(w2n, x.x, f2loc[c].x);
                f2loc[c].y = fmaf(w2n, x.y, f2loc[c].y);
            }
            f1x += __shfl_xor_sync(0xffffffffu, f1x, 16);
            f1y += __shfl_xor_sync(0xffffffffu, f1y, 16);
            const float* wr = &sbuf[(n - ph*128)*32 + ch*16];
            #pragma unroll
            for (int c = 0; c < 16; ++c) {
                const float wc = wr[c];
                tmploc[c].x = fmaf(wc, f1x, tmploc[c].x);
                tmploc[c].y = fmaf(wc, f1y, tmploc[c].y);
            }
        }
    }

    // ---- deterministic reduction over the 8 n-group warps ----
    // slot layout: sbuf[(c*32 + tloc)*8 + ng], tloc = 2*tl + comp
    __syncthreads();
    #pragma unroll
    for (int c = 0; c < 16; ++c) {
        const int base = (((ch*16 + c)*32) + 2*tl)*8 + ng;
        sbuf[base]     = f2loc[c].x;
        sbuf[base + 8] = f2loc[c].y;
    }
    __syncthreads();
    #pragma unroll
    for (int k = 0; k < 4; ++k) {
        const int o = tid + k*256;
        const int c = o >> 5, t2 = o & 31;
        float s = 0.f;
        #pragma unroll
        for (int g = 0; g < 8; ++g) s += sbuf[(c*32 + t2)*8 + g];
        g_f2[((size_t)b*C_ + c)*T_ + tc*32 + t2] = s;
    }
    __syncthreads();
    #pragma unroll
    for (int c = 0; c < 16; ++c) {
        const int base = (((ch*16 + c)*32) + 2*tl)*8 + ng;
        sbuf[base]     = tmploc[c].x;
        sbuf[base + 8] = tmploc[c].y;
    }
    __syncthreads();
    #pragma unroll
    for (int k = 0; k < 4; ++k) {
        const int o = tid + k*256;
        const int c = o >> 5, t2 = o & 31;
        float s = 0.f;
        #pragma unroll
        for (int g = 0; g < 8; ++g) s += sbuf[(c*32 + t2)*8 + g];
        g_tmp[((size_t)b*C_ + c)*T_ + tc*32 + t2] = s;
    }
}

// ================================================================================
// k0: split v into fp16 hi/lo (padded 512 stride; pad stays zero)
// ================================================================================
__global__ __launch_bounds__(256)
void k0_splitv(const float* __restrict__ v)
{
    const int i = blockIdx.x*256 + threadIdx.x;
    if (i >= T_*T_) return;
    const int t = i / T_, s = i - t*T_;
    const float x = v[i];
    const __half hi = __float2half_rn(x);
    const __half lo = __float2half_rn(x - __half2float(hi));
    g_vhi[t*512 + s] = hi;
    g_vlo[t*512 + s] = lo;
}

// ================================================================================
// K2: logits -> sigmoid -> fp16 hi/lo, row stride 512 (cols 480..511 stay zero)
// ================================================================================
__global__ __launch_bounds__(480)
void k2_logits(const float* __restrict__ bmat)
{
    __shared__ float tmps[32*32];
    const int s  = threadIdx.x;
    const int tc = blockIdx.x;
    const int b  = blockIdx.y;

    for (int i = s; i < 1024; i += 480) {
        const int c = i >> 5, tt = i & 31;
        tmps[i] = g_tmp[((size_t)b*C_ + c)*T_ + tc*32 + tt];
    }
    __syncthreads();

    float f2r[32];
    #pragma unroll
    for (int c = 0; c < 32; ++c) f2r[c] = g_f2[((size_t)b*C_ + c)*T_ + s];

    for (int tg = 0; tg < 8; ++tg) {
        const int t0 = tc*32 + tg*4;
        float a0 = bmat[(size_t)(t0+0)*T_ + s];
        float a1 = bmat[(size_t)(t0+1)*T_ + s];
        float a2 = bmat[(size_t)(t0+2)*T_ + s];
        float a3 = bmat[(size_t)(t0+3)*T_ + s];
        #pragma unroll
        for (int c = 0; c < 32; ++c) {
            float4 tv = *reinterpret_cast<const float4*>(&tmps[c*32 + tg*4]);
            const float f = f2r[c];
            a0 = fmaf(tv.x, f, a0);
            a1 = fmaf(tv.y, f, a1);
            a2 = fmaf(tv.z, f, a2);
            a3 = fmaf(tv.w, f, a3);
        }
        const size_t o = ((size_t)b*T_ + t0)*512 + s;
        float xs[4];
        xs[0] = 1.f/(1.f + __expf(-a0));
        xs[1] = 1.f/(1.f + __expf(-a1));
        xs[2] = 1.f/(1.f + __expf(-a2));
        xs[3] = 1.f/(1.f + __expf(-a3));
        #pragma unroll
        for (int r = 0; r < 4; ++r) {
            const __half hi = __float2half_rn(xs[r]);
            const __half lo = __float2half_rn(xs[r] - __half2float(hi));
            g_Lhi[o + (size_t)r*512] = hi;
            g_Llo[o + (size_t)r*512] = lo;
        }
    }
}

// ================================================================================
// K3: out2[b,t,u] = sum_s v[t,s]*L[b,s,u]   via fp16-split mma.m16n8k16
// CTA 128x128, 8 warps (2x4) of 64x32 warp tiles. KC=32, cp.async double buffer.
// Reg-lean fragment flow -> 2 CTAs/SM.
// ================================================================================
#define KC 32
#define NKCH (T_/KC)            // 15
#define A_STRIDE 40             // halves per A row (conflict-free)
#define B_STRIDE 136            // halves per B row (conflict-free for trans)
#define A_BUF_B (128*A_STRIDE*2)   // 10240 bytes per precision
#define B_BUF_B (KC*B_STRIDE*2)    // 8704 bytes per precision
#define STAGE_B (2*A_BUF_B + 2*B_BUF_B)   // 37888
#define SMEM_K3 (2*STAGE_B)               // 75776

__device__ __forceinline__ void cpasync16(uint32_t dst, const void* src) {
    asm volatile("cp.async.cg.shared.global [%0], [%1], 16;\n" :: "r"(dst), "l"(src));
}
__device__ __forceinline__ void ldsm_x4(uint32_t* r, uint32_t addr) {
    asm volatile("ldmatrix.sync.aligned.m8n8.x4.shared.b16 {%0,%1,%2,%3}, [%4];"
                 : "=r"(r[0]), "=r"(r[1]), "=r"(r[2]), "=r"(r[3]) : "r"(addr));
}
__device__ __forceinline__ void ldsm_x4t(uint32_t* r, uint32_t addr) {
    asm volatile("ldmatrix.sync.aligned.m8n8.x4.trans.shared.b16 {%0,%1,%2,%3}, [%4];"
                 : "=r"(r[0]), "=r"(r[1]), "=r"(r[2]), "=r"(r[3]) : "r"(addr));
}
__device__ __forceinline__ void mma16816(float* d, const uint32_t* a, const uint32_t* b) {
    asm volatile(
        "mma.sync.aligned.m16n8k16.row.col.f32.f16.f16.f32 "
        "{%0,%1,%2,%3}, {%4,%5,%6,%7}, {%8,%9}, {%0,%1,%2,%3};"
        : "+f"(d[0]), "+f"(d[1]), "+f"(d[2]), "+f"(d[3])
        : "r"(a[0]), "r"(a[1]), "r"(a[2]), "r"(a[3]), "r"(b[0]), "r"(b[1]));
}

__global__ __launch_bounds__(256, 2)
void k3_fp16()
{
    extern __shared__ char smem[];
    const uint32_t smb = (uint32_t)__cvta_generic_to_shared(smem);

    const int tid  = threadIdx.x;
    const int lane = tid & 31;
    const int wid  = tid >> 5;
    const int wm   = wid >> 2;            // 0..1
    const int wn   = wid & 3;             // 0..3
    const int u0   = blockIdx.x * 128;
    const int t0   = blockIdx.y * 128;
    const int b    = blockIdx.z;

    float acc[4][4][4];
    #pragma unroll
    for (int i = 0; i < 4; ++i)
        #pragma unroll
        for (int j = 0; j < 4; ++j)
            #pragma unroll
            for (int q = 0; q < 4; ++q) acc[i][j][q] = 0.f;

    const int arow = tid >> 1;
    const int aq   = (tid & 1) * 2;
    const int brow = tid >> 3;
    const int bq   = (tid & 7) * 2;

    auto load_chunk = [&](int ch, int st) {
        const int k0e = ch * KC;
        const uint32_t abase = smb + st*STAGE_B;
        const uint32_t bbase = abase + 2*A_BUF_B;
        #pragma unroll
        for (int p = 0; p < 2; ++p) {
            const __half* srcA = (p ? g_vlo : g_vhi) + (size_t)(t0 + arow)*512 + k0e;
            const uint32_t adst = abase + p*A_BUF_B + (arow*A_STRIDE)*2;
            cpasync16(adst + aq*16,        srcA + aq*8);
            cpasync16(adst + (aq+1)*16,    srcA + (aq+1)*8);
            const __half* srcB = (p ? g_Llo : g_Lhi) + ((size_t)b*T_ + k0e + brow)*512 + u0;
            const uint32_t bdst = bbase + p*B_BUF_B + (brow*B_STRIDE)*2;
            cpasync16(bdst + bq*16,        srcB + bq*8);
            cpasync16(bdst + (bq+1)*16,    srcB + (bq+1)*8);
        }
        asm volatile("cp.async.commit_group;\n" ::);
    };

    load_chunk(0, 0);

    for (int ch = 0; ch < NKCH; ++ch) {
        const int st = ch & 1;
        if (ch + 1 < NKCH) {
            load_chunk(ch + 1, st ^ 1);
            asm volatile("cp.async.wait_group 1;\n" ::);
        } else {
            asm volatile("cp.async.wait_group 0;\n" ::);
        }
        __syncthreads();

        const uint32_t abase = smb + st*STAGE_B;
        const uint32_t bbase = abase + 2*A_BUF_B;

        #pragma unroll
        for (int kk = 0; kk < 2; ++kk) {
            const int kc = kk * 16;
            // ---- B fragments for all 4 j (16 regs per precision) ----
            uint32_t bh[4][2], bl[4][2];
            {
                const int r  = lane & 7;
                const int tb = lane >> 3;
                const int rowk = kc + (tb & 1)*8 + r;
                #pragma unroll
                for (int jj = 0; jj < 2; ++jj) {
                    const int coln = wn*32 + jj*16 + (tb >> 1)*8;
                    const uint32_t ba = (uint32_t)(rowk*B_STRIDE + coln)*2;
                    uint32_t rh[4], rl[4];
                    ldsm_x4t(rh, bbase + ba);
                    ldsm_x4t(rl, bbase + B_BUF_B + ba);
                    bh[jj*2  ][0] = rh[0]; bh[jj*2  ][1] = rh[1];
                    bh[jj*2+1][0] = rh[2]; bh[jj*2+1][1] = rh[3];
                    bl[jj*2  ][0] = rl[0]; bl[jj*2  ][1] = rl[1];
                    bl[jj*2+1][0] = rl[2]; bl[jj*2+1][1] = rl[3];
                }
            }
            // ---- A fragments per-i (short live range), 12 MMAs each ----
            {
                const int r  = lane & 7;
                const int tb = lane >> 3;
                const int rr = (tb & 1)*8 + r;
                const int cc = kc + (tb >> 1)*8;
                #pragma unroll
                for (int i = 0; i < 4; ++i) {
                    uint32_t ah[4], al[4];
                    const int row = wm*64 + i*16 + rr;
                    const uint32_t aa = (uint32_t)(row*A_STRIDE + cc)*2;
                    ldsm_x4(ah, abase + aa);
                    ldsm_x4(al, abase + A_BUF_B + aa);
                    #pragma unroll
                    for (int j = 0; j < 4; ++j) {
                        mma16816(acc[i][j], ah, bh[j]);
                        mma16816(acc[i][j], ah, bl[j]);
                        mma16816(acc[i][j], al, bh[j]);
                    }
                }
            }
        }
        __syncthreads();
    }

    // ---- epilogue ----
    float* ob = g_out2 + (size_t)b*T_*T_;
    #pragma unroll
    for (int i = 0; i < 4; ++i) {
        const int r0 = t0 + wm*64 + i*16 + (lane >> 2);
        #pragma unroll
        for (int j = 0; j < 4; ++j) {
            const int cN = u0 + wn*32 + j*8 + (lane & 3)*2;
            if (cN < T_) {
                if (r0 < T_) {
                    float2 p; p.x = acc[i][j][0]; p.y = acc[i][j][1];
                    *reinterpret_cast<float2*>(&ob[(size_t)r0*T_ + cN]) = p;
                }
                if (r0 + 8 < T_) {
                    float2 p; p.x = acc[i][j][2]; p.y = acc[i][j][3];
                    *reinterpret_cast<float2*>(&ob[(size_t)(r0+8)*T_ + cN]) = p;
                }
            }
        }
    }
}

// ================================================================================
// K4/K5: BatchNorm stats (unchanged)
// ================================================================================
__global__ __launch_bounds__(480)
void k4_stats()
{
    const int u  = threadIdx.x;
    const int ch = blockIdx.x;
    const float* base = g_out2 + (size_t)ch*ROWS_PER_CHUNK*T_ + u;
    float s = 0.f, q = 0.f;
    #pragma unroll 8
    for (int r = 0; r < ROWS_PER_CHUNK; ++r) {
        const float x = base[(size_t)r*T_];
        s += x;
        q = fmaf(x, x, q);
    }
    g_psum  [ch*T_ + u] = s;
    g_psumsq[ch*T_ + u] = q;
}

__global__ __launch_bounds__(128)
void k5_final(const float* __restrict__ gamma, const float* __restrict__ beta)
{
    const int u = blockIdx.x*128 + threadIdx.x;
    if (u >= T_) return;
    float s = 0.f, q = 0.f;
    for (int ch = 0; ch < STAT_CHUNKS; ++ch) { s += g_psum[ch*T_+u]; q += g_psumsq[ch*T_+u]; }
    const float mean = s * (1.f/(float)BT_);
    const float var  = q * (1.f/(float)BT_) - mean*mean;
    const float sc   = gamma[u] * rsqrtf(var + 1e-5f);
    g_scale[u] = sc;
    g_shift[u] = beta[u] - mean*sc;
}

// ================================================================================
// K6: masked softmax (unchanged)
// ================================================================================
__global__ __launch_bounds__(512)
void k6_softmax(const float* __restrict__ mask, float* __restrict__ out)
{
    __shared__ float red[16];
    const int row = blockIdx.x;
    const int t   = row % T_;
    const int tid = threadIdx.x;

    float e = 0.f;
    if (tid < T_) {
        const float x = g_out2[(size_t)row*T_ + tid] * g_scale[tid] + g_shift[tid]
                      + mask[(size_t)t*T_ + tid];
        e = __expf(x);
    }
    float s = e;
    #pragma unroll
    for (int o = 16; o > 0; o >>= 1) s += __shfl_xor_sync(0xffffffffu, s, o);
    if ((tid & 31) == 0) red[tid >> 5] = s;
    __syncthreads();
    if (tid < 32) {
        float v2 = (tid < 16) ? red[tid] : 0.f;
        #pragma unroll
        for (int o = 8; o > 0; o >>= 1) v2 += __shfl_xor_sync(0xffffffffu, v2, o);
        if (tid == 0) red[0] = v2;
    }
    __syncthreads();
    const float inv = 1.f / red[0];
    if (tid < T_) out[(size_t)row*T_ + tid] = e * inv;
}

// ================================================================================
extern "C" void kernel_launch(void* const* d_in, const int* in_sizes, int n_in,
                              void* d_out, int out_size)
{
    const float* seq   = (const float*)d_in[0];
    const float* w1    = (const float*)d_in[1];
    const float* w2    = (const float*)d_in[2];
    const float* w     = (const float*)d_in[3];
    const float* bmat  = (const float*)d_in[4];
    const float* v     = (const float*)d_in[5];
    const float* gamma = (const float*)d_in[6];
    const float* beta  = (const float*)d_in[7];
    const float* mask  = (const float*)d_in[8];
    float* out = (float*)d_out;

    cudaFuncSetAttribute(k3_fp16, cudaFuncAttributeMaxDynamicSharedMemorySize, SMEM_K3);

    k0_splitv <<<(T_*T_ + 255)/256, 256>>>(v);
    k1_fused  <<<dim3(15, 32), 256>>>(seq, w1, w2, w);
    k2_logits <<<dim3(15, 32), 480>>>(bmat);
    k3_fp16   <<<dim3(4, 4, 32), 256, SMEM_K3>>>();
    k4_stats  <<<STAT_CHUNKS, 480>>>();
    k5_final  <<<4, 128>>>(gamma, beta);
    k6_softmax<<<BT_, 512>>>(mask, out);
}

// round 6
// speedup vs baseline: 1.5744x; 1.1719x over previous
#include <cuda_runtime.h>
#include <cuda_fp16.h>
#include <cstddef>
#include <cstdint>

#define B_ 32
#define C_ 32
#define N_ 512
#define T_ 480
#define BT_ (B_*T_)          // 15360

// ---------------- scratch (static device arrays; no allocations) ----------------
__device__ float g_f2[B_*C_*T_];
__device__ float g_tmp[B_*C_*T_];
__device__ float g_out2[(size_t)B_*T_*T_];          // [b][t][u] f32   28 MB
__device__ __half g_vhi[512*512];                   // v split, zero-padded
__device__ __half g_vlo[512*512];
__device__ __half g_Lhi[(size_t)B_*T_*512];         // logits split [b][s][u], u-stride 512
__device__ __half g_Llo[(size_t)B_*T_*512];
__device__ float g_ps[32*4*512];                    // per (b, t-tile) partial sums over t
__device__ float g_pq[32*4*512];                    // per (b, t-tile) partial sumsq
__device__ float g_scale[T_];
__device__ float g_shift[T_];

// ================================================================================
// K1: single pass over seq -> f2 and tmp (at its DRAM-pattern ceiling; +__ldcs)
// ================================================================================
__global__ __launch_bounds__(256, 2)
void k1_fused(const float* __restrict__ seq, const float* __restrict__ w1,
              const float* __restrict__ w2, const float* __restrict__ w)
{
    __shared__ float sbuf[8192];
    __shared__ float w1sh[32];
    __shared__ float w2s[N_];

    const int tid  = threadIdx.x;
    const int lane = tid & 31;
    const int ng   = tid >> 5;
    const int tl   = lane & 15;
    const int ch   = lane >> 4;
    const int tc   = blockIdx.x;
    const int b    = blockIdx.y;

    if (tid < 32) w1sh[tid] = w1[tid];
    for (int i = tid; i < N_; i += 256) w2s[i] = w2[i];

    float2 f2loc[16], tmploc[16];
    #pragma unroll
    for (int c = 0; c < 16; ++c) {
        f2loc[c].x = 0.f; f2loc[c].y = 0.f;
        tmploc[c].x = 0.f; tmploc[c].y = 0.f;
    }

    const float2* seqb = reinterpret_cast<const float2*>(seq + (size_t)b*C_*N_*T_)
                         + tc*16 + tl + (size_t)ch*16*122880;

    for (int ph = 0; ph < 4; ++ph) {
        __syncthreads();
        for (int i = tid; i < 128*32; i += 256)
            sbuf[i] = w[ph*128*32 + i];
        __syncthreads();

        const int nbase = ph*128 + ng*16;
        for (int j = 0; j < 16; ++j) {
            const int n = nbase + j;
            const float2* p = seqb + (size_t)n*240;
            const float w2n = w2s[n];
            float f1x = 0.f, f1y = 0.f;
            #pragma unroll
            for (int c = 0; c < 16; ++c) {
                const float2 x = __ldcs(&p[(size_t)c*122880]);
                const float w1c = w1sh[ch*16 + c];
                f1x = fmaf(w1c, x.x, f1x);
                f1y = fmaf(w1c, x.y, f1y);
                f2loc[c].x = fmaf(w2n, x.x, f2loc[c].x);
                f2loc[c].y = fmaf(w2n, x.y, f2loc[c].y);
            }
            f1x += __shfl_xor_sync(0xffffffffu, f1x, 16);
            f1y += __shfl_xor_sync(0xffffffffu, f1y, 16);
            const float* wr = &sbuf[(n - ph*128)*32 + ch*16];
            #pragma unroll
            for (int c = 0; c < 16; ++c) {
                const float wc = wr[c];
                tmploc[c].x = fmaf(wc, f1x, tmploc[c].x);
                tmploc[c].y = fmaf(wc, f1y, tmploc[c].y);
            }
        }
    }

    __syncthreads();
    #pragma unroll
    for (int c = 0; c < 16; ++c) {
        const int base = (((ch*16 + c)*32) + 2*tl)*8 + ng;
        sbuf[base]     = f2loc[c].x;
        sbuf[base + 8] = f2loc[c].y;
    }
    __syncthreads();
    #pragma unroll
    for (int k = 0; k < 4; ++k) {
        const int o = tid + k*256;
        const int c = o >> 5, t2 = o & 31;
        float s = 0.f;
        #pragma unroll
        for (int g = 0; g < 8; ++g) s += sbuf[(c*32 + t2)*8 + g];
        g_f2[((size_t)b*C_ + c)*T_ + tc*32 + t2] = s;
    }
    __syncthreads();
    #pragma unroll
    for (int c = 0; c < 16; ++c) {
        const int base = (((ch*16 + c)*32) + 2*tl)*8 + ng;
        sbuf[base]     = tmploc[c].x;
        sbuf[base + 8] = tmploc[c].y;
    }
    __syncthreads();
    #pragma unroll
    for (int k = 0; k < 4; ++k) {
        const int o = tid + k*256;
        const int c = o >> 5, t2 = o & 31;
        float s = 0.f;
        #pragma unroll
        for (int g = 0; g < 8; ++g) s += sbuf[(c*32 + t2)*8 + g];
        g_tmp[((size_t)b*C_ + c)*T_ + tc*32 + t2] = s;
    }
}

// ================================================================================
// k0: split v into fp16 hi/lo (padded 512 stride; pad stays zero)
// ================================================================================
__global__ __launch_bounds__(256)
void k0_splitv(const float* __restrict__ v)
{
    const int i = blockIdx.x*256 + threadIdx.x;
    if (i >= T_*T_) return;
    const int t = i / T_, s = i - t*T_;
    const float x = v[i];
    const __half hi = __float2half_rn(x);
    const __half lo = __float2half_rn(x - __half2float(hi));
    g_vhi[t*512 + s] = hi;
    g_vlo[t*512 + s] = lo;
}

// ================================================================================
// K2: logits -> sigmoid -> fp16 hi/lo, row stride 512 (cols 480..511 stay zero)
// ================================================================================
__global__ __launch_bounds__(480)
void k2_logits(const float* __restrict__ bmat)
{
    __shared__ float tmps[32*32];
    const int s  = threadIdx.x;
    const int tc = blockIdx.x;
    const int b  = blockIdx.y;

    for (int i = s; i < 1024; i += 480) {
        const int c = i >> 5, tt = i & 31;
        tmps[i] = g_tmp[((size_t)b*C_ + c)*T_ + tc*32 + tt];
    }
    __syncthreads();

    float f2r[32];
    #pragma unroll
    for (int c = 0; c < 32; ++c) f2r[c] = g_f2[((size_t)b*C_ + c)*T_ + s];

    for (int tg = 0; tg < 8; ++tg) {
        const int t0 = tc*32 + tg*4;
        float a0 = bmat[(size_t)(t0+0)*T_ + s];
        float a1 = bmat[(size_t)(t0+1)*T_ + s];
        float a2 = bmat[(size_t)(t0+2)*T_ + s];
        float a3 = bmat[(size_t)(t0+3)*T_ + s];
        #pragma unroll
        for (int c = 0; c < 32; ++c) {
            float4 tv = *reinterpret_cast<const float4*>(&tmps[c*32 + tg*4]);
            const float f = f2r[c];
            a0 = fmaf(tv.x, f, a0);
            a1 = fmaf(tv.y, f, a1);
            a2 = fmaf(tv.z, f, a2);
            a3 = fmaf(tv.w, f, a3);
        }
        const size_t o = ((size_t)b*T_ + t0)*512 + s;
        float xs[4];
        xs[0] = 1.f/(1.f + __expf(-a0));
        xs[1] = 1.f/(1.f + __expf(-a1));
        xs[2] = 1.f/(1.f + __expf(-a2));
        xs[3] = 1.f/(1.f + __expf(-a3));
        #pragma unroll
        for (int r = 0; r < 4; ++r) {
            const __half hi = __float2half_rn(xs[r]);
            const __half lo = __float2half_rn(xs[r] - __half2float(hi));
            g_Lhi[o + (size_t)r*512] = hi;
            g_Llo[o + (size_t)r*512] = lo;
        }
    }
}

// ================================================================================
// K3: out2[b,t,u] = sum_s v[t,s]*L[b,s,u]   via fp16-split mma.m16n8k16
// 3-stage cp.async, 1 sync/iter, fused BN partial stats in epilogue.
// ================================================================================
#define KC 32
#define NKCH (T_/KC)            // 15
#define A_STRIDE 40
#define B_STRIDE 136
#define A_BUF_B (128*A_STRIDE*2)   // 10240
#define B_BUF_B (KC*B_STRIDE*2)    // 8704
#define STAGE_B (2*A_BUF_B + 2*B_BUF_B)   // 37888
#define SMEM_K3 (3*STAGE_B)               // 113664

__device__ __forceinline__ void cpasync16(uint32_t dst, const void* src) {
    asm volatile("cp.async.cg.shared.global [%0], [%1], 16;\n" :: "r"(dst), "l"(src));
}
__device__ __forceinline__ void ldsm_x4(uint32_t* r, uint32_t addr) {
    asm volatile("ldmatrix.sync.aligned.m8n8.x4.shared.b16 {%0,%1,%2,%3}, [%4];"
                 : "=r"(r[0]), "=r"(r[1]), "=r"(r[2]), "=r"(r[3]) : "r"(addr));
}
__device__ __forceinline__ void ldsm_x4t(uint32_t* r, uint32_t addr) {
    asm volatile("ldmatrix.sync.aligned.m8n8.x4.trans.shared.b16 {%0,%1,%2,%3}, [%4];"
                 : "=r"(r[0]), "=r"(r[1]), "=r"(r[2]), "=r"(r[3]) : "r"(addr));
}
__device__ __forceinline__ void mma16816(float* d, const uint32_t* a, const uint32_t* b) {
    asm volatile(
        "mma.sync.aligned.m16n8k16.row.col.f32.f16.f16.f32 "
        "{%0,%1,%2,%3}, {%4,%5,%6,%7}, {%8,%9}, {%0,%1,%2,%3};"
        : "+f"(d[0]), "+f"(d[1]), "+f"(d[2]), "+f"(d[3])
        : "r"(a[0]), "r"(a[1]), "r"(a[2]), "r"(a[3]), "r"(b[0]), "r"(b[1]));
}

__global__ __launch_bounds__(256, 2)
void k3_fp16()
{
    extern __shared__ char smem[];
    const uint32_t smb = (uint32_t)__cvta_generic_to_shared(smem);

    const int tid  = threadIdx.x;
    const int lane = tid & 31;
    const int wid  = tid >> 5;
    const int wm   = wid >> 2;            // 0..1
    const int wn   = wid & 3;             // 0..3
    const int u0   = blockIdx.x * 128;
    const int t0   = blockIdx.y * 128;
    const int b    = blockIdx.z;

    float acc[4][4][4];
    #pragma unroll
    for (int i = 0; i < 4; ++i)
        #pragma unroll
        for (int j = 0; j < 4; ++j)
            #pragma unroll
            for (int q = 0; q < 4; ++q) acc[i][j][q] = 0.f;

    const int arow = tid >> 1;
    const int aq   = (tid & 1) * 2;
    const int brow = tid >> 3;
    const int bq   = (tid & 7) * 2;

    auto load_chunk = [&](int chk, int st) {
        const int k0e = chk * KC;
        const uint32_t abase = smb + st*STAGE_B;
        const uint32_t bbase = abase + 2*A_BUF_B;
        #pragma unroll
        for (int p = 0; p < 2; ++p) {
            const __half* srcA = (p ? g_vlo : g_vhi) + (size_t)(t0 + arow)*512 + k0e;
            const uint32_t adst = abase + p*A_BUF_B + (arow*A_STRIDE)*2;
            cpasync16(adst + aq*16,        srcA + aq*8);
            cpasync16(adst + (aq+1)*16,    srcA + (aq+1)*8);
            const __half* srcB = (p ? g_Llo : g_Lhi) + ((size_t)b*T_ + k0e + brow)*512 + u0;
            const uint32_t bdst = bbase + p*B_BUF_B + (brow*B_STRIDE)*2;
            cpasync16(bdst + bq*16,        srcB + bq*8);
            cpasync16(bdst + (bq+1)*16,    srcB + (bq+1)*8);
        }
        asm volatile("cp.async.commit_group;\n" ::);
    };

    load_chunk(0, 0);
    load_chunk(1, 1);

    for (int chk = 0; chk < NKCH; ++chk) {
        const int st = chk % 3;
        if (chk + 1 < NKCH) asm volatile("cp.async.wait_group 1;\n" ::);
        else                asm volatile("cp.async.wait_group 0;\n" ::);
        __syncthreads();
        if (chk + 2 < NKCH) load_chunk(chk + 2, (chk + 2) % 3);

        const uint32_t abase = smb + st*STAGE_B;
        const uint32_t bbase = abase + 2*A_BUF_B;

        #pragma unroll
        for (int kk = 0; kk < 2; ++kk) {
            const int kc = kk * 16;
            uint32_t bh[4][2], bl[4][2];
            {
                const int r  = lane & 7;
                const int tb = lane >> 3;
                const int rowk = kc + (tb & 1)*8 + r;
                #pragma unroll
                for (int jj = 0; jj < 2; ++jj) {
                    const int coln = wn*32 + jj*16 + (tb >> 1)*8;
                    const uint32_t ba = (uint32_t)(rowk*B_STRIDE + coln)*2;
                    uint32_t rh[4], rl[4];
                    ldsm_x4t(rh, bbase + ba);
                    ldsm_x4t(rl, bbase + B_BUF_B + ba);
                    bh[jj*2  ][0] = rh[0]; bh[jj*2  ][1] = rh[1];
                    bh[jj*2+1][0] = rh[2]; bh[jj*2+1][1] = rh[3];
                    bl[jj*2  ][0] = rl[0]; bl[jj*2  ][1] = rl[1];
                    bl[jj*2+1][0] = rl[2]; bl[jj*2+1][1] = rl[3];
                }
            }
            {
                const int r  = lane & 7;
                const int tb = lane >> 3;
                const int rr = (tb & 1)*8 + r;
                const int cc = kc + (tb >> 1)*8;
                #pragma unroll
                for (int i = 0; i < 4; ++i) {
                    uint32_t ah[4], al[4];
                    const int row = wm*64 + i*16 + rr;
                    const uint32_t aa = (uint32_t)(row*A_STRIDE + cc)*2;
                    ldsm_x4(ah, abase + aa);
                    ldsm_x4(al, abase + A_BUF_B + aa);
                    #pragma unroll
                    for (int j = 0; j < 4; ++j) {
                        mma16816(acc[i][j], ah, bh[j]);
                        mma16816(acc[i][j], ah, bl[j]);
                        mma16816(acc[i][j], al, bh[j]);
                    }
                }
            }
        }
    }

    // ---- epilogue 1: out2 stores ----
    float* ob = g_out2 + (size_t)b*T_*T_;
    #pragma unroll
    for (int i = 0; i < 4; ++i) {
        const int r0 = t0 + wm*64 + i*16 + (lane >> 2);
        #pragma unroll
        for (int j = 0; j < 4; ++j) {
            const int cN = u0 + wn*32 + j*8 + (lane & 3)*2;
            if (cN < T_) {
                if (r0 < T_) {
                    float2 p; p.x = acc[i][j][0]; p.y = acc[i][j][1];
                    *reinterpret_cast<float2*>(&ob[(size_t)r0*T_ + cN]) = p;
                }
                if (r0 + 8 < T_) {
                    float2 p; p.x = acc[i][j][2]; p.y = acc[i][j][3];
                    *reinterpret_cast<float2*>(&ob[(size_t)(r0+8)*T_ + cN]) = p;
                }
            }
        }
    }

    // ---- epilogue 2: fused BN partial stats (sum, sumsq over this tile's 128 t) ----
    // Padding rows/cols carry exact zeros -> including them is harmless.
    __syncthreads();                       // mainloop smem reads done; reuse smem
    float* sred = reinterpret_cast<float*>(smem);          // [128][16]
    float* qred = sred + 128*16;                           // [128][16]
    const int slot = wm*8 + (lane >> 2);   // 16 contributors per u column
    #pragma unroll
    for (int j = 0; j < 4; ++j) {
        #pragma unroll
        for (int q = 0; q < 2; ++q) {
            float s = 0.f, qq = 0.f;
            #pragma unroll
            for (int i = 0; i < 4; ++i) {
                const float x0 = acc[i][j][q];
                const float x1 = acc[i][j][q+2];
                s += x0 + x1;
                qq = fmaf(x0, x0, qq);
                qq = fmaf(x1, x1, qq);
            }
            const int ul = wn*32 + j*8 + (lane & 3)*2 + q;
            sred[ul*16 + slot] = s;
            qred[ul*16 + slot] = qq;
        }
    }
    __syncthreads();
    if (tid < 128) {
        float s = 0.f, qq = 0.f;
        #pragma unroll
        for (int k = 0; k < 16; ++k) {
            s  += sred[tid*16 + k];
            qq += qred[tid*16 + k];
        }
        const int dst = ((b*4 + blockIdx.y)*512) + u0 + tid;
        g_ps[dst] = s;
        g_pq[dst] = qq;
    }
}

// ================================================================================
// K5: finalize BN scale/shift from fused partials
// ================================================================================
__global__ __launch_bounds__(128)
void k5_final(const float* __restrict__ gamma, const float* __restrict__ beta)
{
    const int u = blockIdx.x*128 + threadIdx.x;
    if (u >= T_) return;
    float s = 0.f, q = 0.f;
    for (int i = 0; i < 128; ++i) { s += g_ps[i*512 + u]; q += g_pq[i*512 + u]; }
    const float mean = s * (1.f/(float)BT_);
    const float var  = q * (1.f/(float)BT_) - mean*mean;
    const float sc   = gamma[u] * rsqrtf(var + 1e-5f);
    g_scale[u] = sc;
    g_shift[u] = beta[u] - mean*sc;
}

// ================================================================================
// K6: masked softmax (out2 read-once -> __ldcs)
// ================================================================================
__global__ __launch_bounds__(512)
void k6_softmax(const float* __restrict__ mask, float* __restrict__ out)
{
    __shared__ float red[16];
    const int row = blockIdx.x;
    const int t   = row % T_;
    const int tid = threadIdx.x;

    float e = 0.f;
    if (tid < T_) {
        const float x = __ldcs(&g_out2[(size_t)row*T_ + tid]) * g_scale[tid] + g_shift[tid]
                      + mask[(size_t)t*T_ + tid];
        e = __expf(x);
    }
    float s = e;
    #pragma unroll
    for (int o = 16; o > 0; o >>= 1) s += __shfl_xor_sync(0xffffffffu, s, o);
    if ((tid & 31) == 0) red[tid >> 5] = s;
    __syncthreads();
    if (tid < 32) {
        float v2 = (tid < 16) ? red[tid] : 0.f;
        #pragma unroll
        for (int o = 8; o > 0; o >>= 1) v2 += __shfl_xor_sync(0xffffffffu, v2, o);
        if (tid == 0) red[0] = v2;
    }
    __syncthreads();
    const float inv = 1.f / red[0];
    if (tid < T_) out[(size_t)row*T_ + tid] = e * inv;
}

// ================================================================================
extern "C" void kernel_launch(void* const* d_in, const int* in_sizes, int n_in,
                              void* d_out, int out_size)
{
    const float* seq   = (const float*)d_in[0];
    const float* w1    = (const float*)d_in[1];
    const float* w2    = (const float*)d_in[2];
    const float* w     = (const float*)d_in[3];
    const float* bmat  = (const float*)d_in[4];
    const float* v     = (const float*)d_in[5];
    const float* gamma = (const float*)d_in[6];
    const float* beta  = (const float*)d_in[7];
    const float* mask  = (const float*)d_in[8];
    float* out = (float*)d_out;

    cudaFuncSetAttribute(k3_fp16, cudaFuncAttributeMaxDynamicSharedMemorySize, SMEM_K3);

    k0_splitv <<<(T_*T_ + 255)/256, 256>>>(v);
    k1_fused  <<<dim3(15, 32), 256>>>(seq, w1, w2, w);
    k2_logits <<<dim3(15, 32), 480>>>(bmat);
    k3_fp16   <<<dim3(4, 4, 32), 256, SMEM_K3>>>();
    k5_final  <<<4, 128>>>(gamma, beta);
    k6_softmax<<<BT_, 512>>>(mask, out);
}